// round 16
// baseline (speedup 1.0000x reference)
#include <cuda_runtime.h>
#include <cuda_bf16.h>
#include <cuda_fp16.h>
#include <cstdint>
#include <math.h>

#define BQ 1024
#define LQ 128
#define EQ 100
#define HQ 512
#define KH 512          // per-step K: single bf16 h
#define NS 1536         // per-step N per GRU: 3 gates x 512
#define NK_ITERS 8      // 512 / 64
#define KX 128          // precompute K (100 padded)
#define MROWS 131072    // 128 steps x 1024 rows
#define GRPSZ 16        // CTAs per dependency group (one mt, one gru)

// gru smem: 3 stages x (A 16KB + B 12KB) + mbarriers + Gx tile
#define STG_STRIDE 28672
#define SM_FULL  86016
#define SM_EMPTY (86016 + 24)
#define SM_GXBUF 86144
#define GX_ROWB  208
#define SMEM_STEP (SM_GXBUF + 128 * GX_ROWB)   // 112,768 B

// gx_gemm v2 smem: B chunks (2x12KB) + A stages (2x16KB) + C staging
#define GXB_B0 0
#define GXB_B1 12288
#define GXB_A0 24576
#define GXB_A1 40960
#define GXB_CS 57344
#define CS_STRIDE 104
#define SMEM_GX (GXB_CS + 128 * CS_STRIDE * 2)   // 83,968 B

// ---- device scratch ----
__device__ __align__(128) __nv_bfloat16 g_Ah[2][2][BQ][KH];
__device__ __align__(128) __nv_bfloat16 g_Wh[2][NS][KH];
__device__ __align__(128) __nv_bfloat16 g_Wx[2][NS][KX];
__device__ __align__(128) __nv_bfloat16 g_AX[2][MROWS][KX];
__device__ __align__(128) __half        g_Gx[2][MROWS][NS];
__device__ __align__(128) float         g_biasH[2][NS];
__device__ __align__(128) float         g_biasX[2][NS];
__device__ __align__(128) float         g_Hf[2][2][BQ][HQ];
__device__ __align__(128) float         g_S[BQ][BQ];
__device__ __align__(128) int g_barGrp[2][8];

// ---- asm helpers ----
#define LDSM4(R0,R1,R2,R3,ADDR) \
  asm volatile("ldmatrix.sync.aligned.m8n8.x4.shared.b16 {%0,%1,%2,%3},[%4];" \
    : "=r"(R0),"=r"(R1),"=r"(R2),"=r"(R3) : "r"(ADDR))

#define MMA16816(C,A0,A1,A2,A3,B0,B1) \
  asm volatile("mma.sync.aligned.m16n8k16.row.col.f32.bf16.bf16.f32 " \
    "{%0,%1,%2,%3},{%4,%5,%6,%7},{%8,%9},{%0,%1,%2,%3};" \
    : "+f"(C[0]),"+f"(C[1]),"+f"(C[2]),"+f"(C[3]) \
    : "r"(A0),"r"(A1),"r"(A2),"r"(A3),"r"(B0),"r"(B1))

#define CPASYNC16(DST,SRC) \
  asm volatile("cp.async.cg.shared.global [%0],[%1],16;" :: "r"(DST),"l"(SRC))
#define CPCOMMIT asm volatile("cp.async.commit_group;" ::: "memory")

#define CPASYNC_ARRIVE(MBAR) \
  asm volatile("cp.async.mbarrier.arrive.noinc.shared::cta.b64 [%0];" :: "r"(MBAR) : "memory")

#define MBARRIER_INIT(addr, cnt) \
  asm volatile("mbarrier.init.shared.b64 [%0], %1;" :: "r"(addr), "r"(cnt) : "memory")
#define MBARRIER_ARRIVE(addr) \
  asm volatile("mbarrier.arrive.shared::cta.b64 _, [%0];" :: "r"(addr) : "memory")

#define MBARRIER_WAIT_PARITY(addr, par) do { \
    uint32_t _m = (addr), _p = (par), _done; \
    asm volatile("{\n\t.reg .pred p;\n\tmbarrier.try_wait.parity.acquire.cta.shared::cta.b64 p, [%1], %2;\n\tselp.b32 %0,1,0,p;\n\t}" \
        : "=r"(_done) : "r"(_m), "r"(_p) : "memory"); \
    if (!_done) { \
        asm volatile("{\n\t.reg .pred P1;\n\tWL_%=:\n\tmbarrier.try_wait.parity.acquire.cta.shared::cta.b64 P1, [%0], %1, 0x989680;\n\t@P1 bra.uni WD_%=;\n\tbra.uni WL_%=;\n\tWD_%=:\n\t}" \
            :: "r"(_m), "r"(_p) : "memory"); \
    } \
} while (0)

// ---------------------------------------------------------------------------
// Column layout (per GRU, N=1536): wgrp=n/48, c=n%48, ni=c>>3, jj=c&7,
// gate=ni>>1 (0=r,1=z,2=nh), h=wgrp*16+(((ni&1)<<3)|jj), grow=gate*512+h.
// ---------------------------------------------------------------------------
__global__ void pack_weights(const float* __restrict__ Wih0, const float* __restrict__ Whh0,
                             const float* __restrict__ bih0, const float* __restrict__ bhh0,
                             const float* __restrict__ Wih1, const float* __restrict__ Whh1,
                             const float* __restrict__ bih1, const float* __restrict__ bhh1) {
    const long totalWh = 2L * NS * KH;
    for (long idx = (long)blockIdx.x * blockDim.x + threadIdx.x; idx < totalWh;
         idx += (long)gridDim.x * blockDim.x) {
        int g   = (int)(idx / (NS * (long)KH));
        int rem = (int)(idx - (long)g * NS * KH);
        int n = rem / KH;
        int k = rem - n * KH;
        int wgrp = n / 48, c = n - wgrp * 48;
        int ni = c >> 3, jj = c & 7;
        int gate = ni >> 1;
        int h = wgrp * 16 + (((ni & 1) << 3) | jj);
        int grow = gate * 512 + h;
        const float* Whh = g ? Whh1 : Whh0;
        g_Wh[g][n][k] = __float2bfloat16(Whh[grow * HQ + k]);
    }
    const long totalWx = 2L * NS * KX;
    for (long idx = (long)blockIdx.x * blockDim.x + threadIdx.x; idx < totalWx;
         idx += (long)gridDim.x * blockDim.x) {
        int g   = (int)(idx / (NS * (long)KX));
        int rem = (int)(idx - (long)g * NS * KX);
        int n = rem / KX;
        int e = rem - n * KX;
        int wgrp = n / 48, c = n - wgrp * 48;
        int ni = c >> 3, jj = c & 7;
        int gate = ni >> 1;
        int h = wgrp * 16 + (((ni & 1) << 3) | jj);
        int grow = gate * 512 + h;
        const float* Wih = g ? Wih1 : Wih0;
        g_Wx[g][n][e] = __float2bfloat16(e < EQ ? Wih[grow * EQ + e] : 0.f);
    }
    for (int idx = blockIdx.x * blockDim.x + threadIdx.x; idx < 2 * NS;
         idx += gridDim.x * blockDim.x) {
        int g = idx / NS;
        int n = idx - g * NS;
        int wgrp = n / 48, c = n - wgrp * 48;
        int ni = c >> 3, jj = c & 7;
        int gate = ni >> 1;
        int h = wgrp * 16 + (((ni & 1) << 3) | jj);
        int grow = gate * 512 + h;
        const float* bih = g ? bih1 : bih0;
        const float* bhh = g ? bhh1 : bhh0;
        g_biasH[g][n] = bhh[grow];
        g_biasX[g][n] = bih[grow] + (gate < 2 ? bhh[grow] : 0.f);
    }
}

// Build A_X rows: row' = s*1024 + R holds x_{t=L-1-s, R} (bf16, pad 0).
__global__ void build_ax(const int* __restrict__ tok0, const int* __restrict__ tok1,
                         const float* __restrict__ emb0, const float* __restrict__ emb1) {
    const long total = 2L * MROWS * KX;
    for (long idx = (long)blockIdx.x * blockDim.x + threadIdx.x; idx < total;
         idx += (long)gridDim.x * blockDim.x) {
        int g    = (int)(idx / (MROWS * (long)KX));
        long rem = idx - (long)g * MROWS * KX;
        int rowp = (int)(rem >> 7);
        int e    = (int)(rem & 127);
        int s = rowp >> 10, R = rowp & 1023;
        float v = 0.f;
        if (e < EQ) {
            const int*   tok = g ? tok1 : tok0;
            const float* emb = g ? emb1 : emb0;
            int ti = tok[R * LQ + (LQ - 1 - s)];
            v = emb[ti * EQ + e];
        }
        g_AX[g][rowp][e] = __float2bfloat16(v);
    }
}

// Zero h state; reset group step barriers
__global__ void init_state() {
    if (blockIdx.x == 0 && threadIdx.x < 16)
        g_barGrp[threadIdx.x >> 3][threadIdx.x & 7] = 0;
    const int totalA = 2 * BQ * KH;
    for (int idx = blockIdx.x * blockDim.x + threadIdx.x; idx < totalA;
         idx += gridDim.x * blockDim.x) {
        int g = idx / (BQ * KH);
        int rem = idx - g * BQ * KH;
        g_Ah[0][g][rem / KH][rem % KH] = __float2bfloat16(0.f);
    }
    const int totalH = 2 * BQ * HQ;
    for (int idx = blockIdx.x * blockDim.x + threadIdx.x; idx < totalH;
         idx += gridDim.x * blockDim.x) {
        int g = idx / (BQ * HQ);
        int rem = idx - g * BQ * HQ;
        g_Hf[0][g][rem / HQ][rem % HQ] = 0.f;
    }
}

// ---------------------------------------------------------------------------
// Precompute Gx = A_X @ Wx^T + biasX (fp16 out). v2: each CTA does TWO
// 128-row m-halves reusing its B tile; half-1 A load overlaps half-0 epilogue.
// grid (n=16, m=512, 2).
// ---------------------------------------------------------------------------
__global__ __launch_bounds__(256) void gx_gemm() {
    extern __shared__ char smem[];
    const uint32_t sbase = (uint32_t)__cvta_generic_to_shared(smem);
    const int g      = blockIdx.z;
    const int m_base = blockIdx.y * 256;
    const int n0     = blockIdx.x * 96;
    const int tid = threadIdx.x;
    const int lane = tid & 31;
    const int warp = tid >> 5;
    const int wm = (warp >> 1) << 5;
    const int wn = (warp & 1) * 48;

    // prologue: B both chunks + A half-0 both stages
#pragma unroll
    for (int st = 0; st < 2; st++) {
#pragma unroll
        for (int p = 0; p < 3; p++) {
            int unit = tid + 256 * p;             // 768 units: 96 rows x 8
            int r = unit >> 3, c = unit & 7;
            uint32_t dst = sbase + (st ? GXB_B1 : GXB_B0)
                         + (uint32_t)(r * 128 + ((c ^ (r & 7)) << 4));
            CPASYNC16(dst, &g_Wx[g][n0 + r][st * 64 + c * 8]);
        }
#pragma unroll
        for (int p = 0; p < 4; p++) {
            int unit = tid + 256 * p;             // 1024 units: 128 rows x 8
            int r = unit >> 3, c = unit & 7;
            uint32_t dst = sbase + (st ? GXB_A1 : GXB_A0)
                         + (uint32_t)(r * 128 + ((c ^ (r & 7)) << 4));
            CPASYNC16(dst, &g_AX[g][m_base + r][st * 64 + c * 8]);
        }
    }
    CPCOMMIT;
    asm volatile("cp.async.wait_group 0;" ::: "memory");
    __syncthreads();

    __half* Cs = (__half*)(smem + GXB_CS);

#pragma unroll
    for (int half = 0; half < 2; half++) {
        float acc[2][6][4];
#pragma unroll
        for (int mi = 0; mi < 2; mi++)
#pragma unroll
            for (int ni = 0; ni < 6; ni++)
#pragma unroll
                for (int q = 0; q < 4; q++) acc[mi][ni][q] = 0.f;

#pragma unroll
        for (int it = 0; it < 2; it++) {
            const uint32_t aB = sbase + (it ? GXB_A1 : GXB_A0);
            const uint32_t bB = sbase + (it ? GXB_B1 : GXB_B0);
#pragma unroll
            for (int kc = 0; kc < 4; kc++) {
                uint32_t a[2][4];
#pragma unroll
                for (int mi = 0; mi < 2; mi++) {
                    int rrow = wm + mi * 16 + (lane & 15);
                    int uc = kc * 2 + (lane >> 4);
                    uint32_t addr = aB + (uint32_t)(rrow * 128 + ((uc ^ (rrow & 7)) << 4));
                    LDSM4(a[mi][0], a[mi][1], a[mi][2], a[mi][3], addr);
                }
                uint32_t b[3][4];
#pragma unroll
                for (int jj = 0; jj < 3; jj++) {
                    int rrow = wn + 16 * jj + (lane & 7) + ((lane >> 4) << 3);
                    int uc = kc * 2 + ((lane >> 3) & 1);
                    uint32_t addr = bB + (uint32_t)(rrow * 128 + ((uc ^ (rrow & 7)) << 4));
                    LDSM4(b[jj][0], b[jj][1], b[jj][2], b[jj][3], addr);
                }
#pragma unroll
                for (int mi = 0; mi < 2; mi++)
#pragma unroll
                    for (int ni = 0; ni < 6; ni++) {
                        int j = ni >> 1, hh = (ni & 1) << 1;
                        MMA16816(acc[mi][ni], a[mi][0], a[mi][1], a[mi][2], a[mi][3],
                                 b[j][hh], b[j][hh + 1]);
                    }
            }
        }

        __syncthreads();   // all warps done reading A stages
        if (half == 0) {
#pragma unroll
            for (int st = 0; st < 2; st++)
#pragma unroll
                for (int p = 0; p < 4; p++) {
                    int unit = tid + 256 * p;
                    int r = unit >> 3, c = unit & 7;
                    uint32_t dst = sbase + (st ? GXB_A1 : GXB_A0)
                                 + (uint32_t)(r * 128 + ((c ^ (r & 7)) << 4));
                    CPASYNC16(dst, &g_AX[g][m_base + 128 + r][st * 64 + c * 8]);
                }
            CPCOMMIT;
        }

#pragma unroll
        for (int mi = 0; mi < 2; mi++)
#pragma unroll
            for (int ni = 0; ni < 6; ni++)
#pragma unroll
                for (int qh = 0; qh < 2; qh++) {
                    int lr  = wm + mi * 16 + (lane >> 2) + qh * 8;
                    int col = wn + ni * 8 + (lane & 3) * 2;
                    float v0 = acc[mi][ni][qh * 2 + 0] + g_biasX[g][n0 + col];
                    float v1 = acc[mi][ni][qh * 2 + 1] + g_biasX[g][n0 + col + 1];
                    *(__half2*)&Cs[lr * CS_STRIDE + col] = __floats2half2_rn(v0, v1);
                }
        __syncthreads();
#pragma unroll
        for (int p = 0; p < 6; p++) {
            int unit = tid + 256 * p;
            int r = unit / 12, c = unit - r * 12;
            uint4 v = *(const uint4*)&Cs[r * CS_STRIDE + c * 8];
            *(uint4*)&g_Gx[g][m_base + half * 128 + r][n0 + c * 8] = v;
        }

        if (half == 0) {
            asm volatile("cp.async.wait_group 0;" ::: "memory");
            __syncthreads();
        }
    }
}

// ---------------------------------------------------------------------------
// PERSISTENT GRU: all 128 steps; per-group barrier; mbarrier pipeline state
// carried ACROSS steps (init once, no per-step reinit). 256 CTAs, 2/SM.
// ---------------------------------------------------------------------------
__global__ __launch_bounds__(256, 2) void gru_persistent() {
    extern __shared__ char smem[];
    const uint32_t sbase = (uint32_t)__cvta_generic_to_shared(smem);
    const int g     = blockIdx.z;
    const int mt    = blockIdx.x;
    const int m0    = mt * 128;
    const int n0    = blockIdx.y * 96;
    const int tid   = threadIdx.x;
    const int lane  = tid & 31;
    const int warp  = tid >> 5;
    const int wm    = (warp >> 1) << 5;
    const int wn    = (warp & 1) * 48;
    const int wgrp  = blockIdx.y * 2 + (warp & 1);
    const uint32_t gxbuf = sbase + SM_GXBUF;
    int* barp = &g_barGrp[g][mt];

    uint32_t aDst[4], aOff[4];
#pragma unroll
    for (int p = 0; p < 4; p++) {
        int unit = tid + 256 * p;
        int r = unit >> 3, c = unit & 7;
        aDst[p] = (uint32_t)(r * 128 + ((c ^ (r & 7)) << 4));
        aOff[p] = (uint32_t)((r * KH + c * 8) * 2);
    }
    uint32_t bDst[3], bOff[3];
#pragma unroll
    for (int p = 0; p < 3; p++) {
        int unit = tid + 256 * p;
        int r = unit >> 3, c = unit & 7;
        bDst[p] = (uint32_t)(r * 128 + ((c ^ (r & 7)) << 4));
        bOff[p] = (uint32_t)((r * KH + c * 8) * 2);
    }
    const __nv_bfloat16* gW = &g_Wh[g][n0][0];

    // init mbarriers ONCE
    if (tid == 0) {
#pragma unroll
        for (int st = 0; st < 3; st++) {
            MBARRIER_INIT(sbase + SM_FULL  + 8 * st, 256);
            MBARRIER_INIT(sbase + SM_EMPTY + 8 * st, 8);
        }
    }
    __syncthreads();

#define STAGE_CP(BUF, KOFF, GAPTR) do { \
    uint32_t _aB = sbase + (uint32_t)(BUF) * STG_STRIDE; \
    uint32_t _bB = _aB + 16384; \
    uint32_t _ko = (uint32_t)(KOFF) * 2; \
    CPASYNC16(_aB + aDst[0], (const char*)(GAPTR) + aOff[0] + _ko); \
    CPASYNC16(_aB + aDst[1], (const char*)(GAPTR) + aOff[1] + _ko); \
    CPASYNC16(_aB + aDst[2], (const char*)(GAPTR) + aOff[2] + _ko); \
    CPASYNC16(_aB + aDst[3], (const char*)(GAPTR) + aOff[3] + _ko); \
    CPASYNC16(_bB + bDst[0], (const char*)gW + bOff[0] + _ko); \
    CPASYNC16(_bB + bDst[1], (const char*)gW + bOff[1] + _ko); \
    CPASYNC16(_bB + bDst[2], (const char*)gW + bOff[2] + _ko); \
    CPASYNC_ARRIVE(sbase + SM_FULL + 8 * (BUF)); \
} while (0)

    // pipeline state persistent across steps
    int fill_n = 0;
    int cbuf = 0, cpar = 0;
    int rbuf = 0;
    int ebuf = 0, epar = 0;

#define FILL_STAGE(KOFF, GAPTR) do { \
    if (fill_n >= 3) { \
        MBARRIER_WAIT_PARITY(sbase + SM_EMPTY + 8 * ebuf, epar); \
        if (++ebuf == 3) { ebuf = 0; epar ^= 1; } \
    } \
    STAGE_CP(rbuf, (KOFF), GAPTR); \
    if (++rbuf == 3) rbuf = 0; \
    fill_n++; \
} while (0)

    for (int s = 0; s < LQ; s++) {
        const int cur = s & 1;
        const int nxt = cur ^ 1;
        const __nv_bfloat16* gA = &g_Ah[cur][g][m0][0];

        FILL_STAGE(0, gA);
        FILL_STAGE(64, gA);

        // ---- Gx epilogue-tile prefetch (overlaps the whole main loop) ----
        {
            const char* gxsrc = (const char*)&g_Gx[g][(s << 10) + m0][n0];
#pragma unroll
            for (int p = 0; p < 6; p++) {
                int unit = tid + 256 * p;
                int r = unit / 12, c = unit - r * 12;
                CPASYNC16(gxbuf + (uint32_t)(r * GX_ROWB + c * 16),
                          gxsrc + (size_t)r * (NS * 2) + c * 16);
            }
            CPCOMMIT;
        }

        float acc[2][6][4];
#pragma unroll
        for (int mi = 0; mi < 2; mi++)
#pragma unroll
            for (int ni = 0; ni < 6; ni++)
#pragma unroll
                for (int q = 0; q < 4; q++) acc[mi][ni][q] = 0.f;

        for (int i = 0; i < NK_ITERS; i++) {
            MBARRIER_WAIT_PARITY(sbase + SM_FULL + 8 * cbuf, cpar);

            const uint32_t aB = sbase + (uint32_t)cbuf * STG_STRIDE;
            const uint32_t bB = aB + 16384;

#pragma unroll
            for (int kc = 0; kc < 4; kc++) {
                uint32_t a[2][4];
#pragma unroll
                for (int mi = 0; mi < 2; mi++) {
                    int rrow = wm + mi * 16 + (lane & 15);
                    int uc = kc * 2 + (lane >> 4);
                    uint32_t addr = aB + (uint32_t)(rrow * 128 + ((uc ^ (rrow & 7)) << 4));
                    LDSM4(a[mi][0], a[mi][1], a[mi][2], a[mi][3], addr);
                }
                uint32_t b[3][4];
#pragma unroll
                for (int jj = 0; jj < 3; jj++) {
                    int rrow = wn + 16 * jj + (lane & 7) + ((lane >> 4) << 3);
                    int uc = kc * 2 + ((lane >> 3) & 1);
                    uint32_t addr = bB + (uint32_t)(rrow * 128 + ((uc ^ (rrow & 7)) << 4));
                    LDSM4(b[jj][0], b[jj][1], b[jj][2], b[jj][3], addr);
                }
#pragma unroll
                for (int mi = 0; mi < 2; mi++)
#pragma unroll
                    for (int ni = 0; ni < 6; ni++) {
                        int j = ni >> 1, hh = (ni & 1) << 1;
                        MMA16816(acc[mi][ni], a[mi][0], a[mi][1], a[mi][2], a[mi][3],
                                 b[j][hh], b[j][hh + 1]);
                    }
            }
            __syncwarp();
            if (lane == 0) MBARRIER_ARRIVE(sbase + SM_EMPTY + 8 * cbuf);
            if (++cbuf == 3) { cbuf = 0; cpar ^= 1; }

            if (i + 2 < NK_ITERS) FILL_STAGE((i + 2) * 64, gA);
        }

        asm volatile("cp.async.wait_group 0;" ::: "memory");
        __syncthreads();

        // ---- epilogue: gates from Gh (regs) + Gx (smem) ----
#pragma unroll
        for (int mi = 0; mi < 2; mi++)
#pragma unroll
            for (int sH = 0; sH < 2; sH++)
#pragma unroll
                for (int qh = 0; qh < 2; qh++) {
                    const int rl = wm + mi * 16 + (lane >> 2) + qh * 8;
                    const int R  = m0 + rl;
                    const int jb = (lane & 3) * 2;
                    const int cl = wn + sH * 8 + jb;
                    const char* gxp = smem + SM_GXBUF + rl * GX_ROWB + cl * 2;
                    float2 xr = __half22float2(*(const __half2*)(gxp));
                    float2 xz = __half22float2(*(const __half2*)(gxp + 32));
                    float2 xn = __half22float2(*(const __half2*)(gxp + 64));
                    const int cR = n0 + cl;
                    float bn0 = g_biasH[g][cR + 32];
                    float bn1 = g_biasH[g][cR + 33];
                    const int hb = wgrp * 16 + sH * 8 + jb;
                    float2 hov = __ldcg((const float2*)&g_Hf[cur][g][R][hb]);
                    float hn2[2];
#pragma unroll
                    for (int qp = 0; qp < 2; qp++) {
                        const int q = qh * 2 + qp;
                        float GhR = acc[mi][0 + sH][q];
                        float GhZ = acc[mi][2 + sH][q];
                        float GhN = acc[mi][4 + sH][q];
                        float gxrv = qp ? xr.y : xr.x;
                        float gxzv = qp ? xz.y : xz.x;
                        float gxnv = qp ? xn.y : xn.x;
                        float bnv  = qp ? bn1 : bn0;
                        float ho   = qp ? hov.y : hov.x;
                        float rr = 1.f / (1.f + __expf(-(GhR + gxrv)));
                        float zz = 1.f / (1.f + __expf(-(GhZ + gxzv)));
                        float pre = gxnv + rr * (GhN + bnv);
                        float ex = __expf(-2.f * fabsf(pre));
                        float nn = copysignf((1.f - ex) / (1.f + ex), pre);
                        hn2[qp] = (1.f - zz) * nn + zz * ho;
                    }
                    *(float2*)&g_Hf[nxt][g][R][hb] = make_float2(hn2[0], hn2[1]);
                    __nv_bfloat162 hi2;
                    hi2.x = __float2bfloat16(hn2[0]);
                    hi2.y = __float2bfloat16(hn2[1]);
                    *(__nv_bfloat162*)&g_Ah[nxt][g][R][hb] = hi2;
                }

        // ---- per-group step barrier (16 CTAs sharing (mt, gru)) ----
        if (s < LQ - 1) {
            __threadfence();
            __syncthreads();
            if (tid == 0) {
                atomicAdd(barp, 1);
                while (atomicAdd(barp, 0) < GRPSZ * (s + 1)) __nanosleep(64);
            }
            __syncthreads();
        }
    }
}

// ---------------------------------------------------------------------------
// S = hc @ hr^T (fp32, K=512) + row softmax
// ---------------------------------------------------------------------------
__global__ __launch_bounds__(256) void score_gemm() {
    const int bm = blockIdx.y;
    const int bn = blockIdx.x;
    __shared__ float As[16][68];
    __shared__ float Bs[16][68];
    const int tid = threadIdx.x;
    const int tx = tid & 15;
    const int ty = tid >> 4;

    float acc[4][4];
#pragma unroll
    for (int i = 0; i < 4; i++)
#pragma unroll
        for (int j = 0; j < 4; j++) acc[i][j] = 0.f;

    const float* Abase = &g_Hf[0][0][bm * 64][0];
    const float* Bbase = &g_Hf[0][1][bn * 64][0];

    for (int k0 = 0; k0 < HQ; k0 += 16) {
#pragma unroll
        for (int i = 0; i < 4; i++) {
            int e = tid + 256 * i;
            int m = e >> 4;
            int k = e & 15;
            As[k][m] = Abase[m * HQ + k0 + k];
            Bs[k][m] = Bbase[m * HQ + k0 + k];
        }
        __syncthreads();
#pragma unroll
        for (int kk = 0; kk < 16; kk++) {
            float4 a4 = *(const float4*)&As[kk][ty * 4];
            float4 b4 = *(const float4*)&Bs[kk][tx * 4];
            float av[4] = {a4.x, a4.y, a4.z, a4.w};
            float bv[4] = {b4.x, b4.y, b4.z, b4.w};
#pragma unroll
            for (int i = 0; i < 4; i++)
#pragma unroll
                for (int j = 0; j < 4; j++) acc[i][j] += av[i] * bv[j];
        }
        __syncthreads();
    }
    const int row = bm * 64 + ty * 4;
    const int col = bn * 64 + tx * 4;
#pragma unroll
    for (int i = 0; i < 4; i++)
#pragma unroll
        for (int j = 0; j < 4; j++) g_S[row + i][col + j] = acc[i][j];
}

__global__ void softmax_rows(float* __restrict__ out) {
    const int row = blockIdx.x;
    __shared__ float red[256];
    const float* Srow = g_S[row];

    float m = -INFINITY;
    for (int j = threadIdx.x; j < BQ; j += 256) m = fmaxf(m, Srow[j]);
    red[threadIdx.x] = m;
    __syncthreads();
    for (int off = 128; off; off >>= 1) {
        if (threadIdx.x < off) red[threadIdx.x] = fmaxf(red[threadIdx.x], red[threadIdx.x + off]);
        __syncthreads();
    }
    m = red[0];
    __syncthreads();

    float sum = 0.f;
    for (int j = threadIdx.x; j < BQ; j += 256) sum += expf(Srow[j] - m);
    red[threadIdx.x] = sum;
    __syncthreads();
    for (int off = 128; off; off >>= 1) {
        if (threadIdx.x < off) red[threadIdx.x] += red[threadIdx.x + off];
        __syncthreads();
    }
    sum = red[0];

    float inv = 1.f / sum;
    for (int j = threadIdx.x; j < BQ; j += 256) out[row * BQ + j] = expf(Srow[j] - m) * inv;
}

// ---------------------------------------------------------------------------
extern "C" void kernel_launch(void* const* d_in, const int* in_sizes, int n_in,
                              void* d_out, int out_size) {
    const int*   ctx     = (const int*)  d_in[0];
    const int*   rep     = (const int*)  d_in[1];
    const float* ctx_emb = (const float*)d_in[2];
    const float* ctx_Wih = (const float*)d_in[3];
    const float* ctx_Whh = (const float*)d_in[4];
    const float* ctx_bih = (const float*)d_in[5];
    const float* ctx_bhh = (const float*)d_in[6];
    const float* rep_emb = (const float*)d_in[7];
    const float* rep_Wih = (const float*)d_in[8];
    const float* rep_Whh = (const float*)d_in[9];
    const float* rep_bih = (const float*)d_in[10];
    const float* rep_bhh = (const float*)d_in[11];

    cudaFuncSetAttribute(gru_persistent, cudaFuncAttributeMaxDynamicSharedMemorySize, SMEM_STEP);
    cudaFuncSetAttribute(gx_gemm,        cudaFuncAttributeMaxDynamicSharedMemorySize, SMEM_GX);

    pack_weights<<<2048, 256>>>(ctx_Wih, ctx_Whh, ctx_bih, ctx_bhh,
                                rep_Wih, rep_Whh, rep_bih, rep_bhh);
    build_ax<<<8192, 256>>>(ctx, rep, ctx_emb, rep_emb);
    init_state<<<2048, 256>>>();

    gx_gemm<<<dim3(16, 512, 2), 256, SMEM_GX>>>();

    gru_persistent<<<dim3(8, 16, 2), 256, SMEM_STEP>>>();

    score_gemm<<<dim3(16, 16), 256>>>();
    softmax_rows<<<BQ, 256>>>((float*)d_out);
}

// round 17
// speedup vs baseline: 1.0859x; 1.0859x over previous
#include <cuda_runtime.h>
#include <cuda_bf16.h>
#include <cuda_fp16.h>
#include <cstdint>
#include <math.h>

#define BQ 1024
#define LQ 128
#define EQ 100
#define HQ 512
#define KH 512          // per-step K: single bf16 h
#define NS 1536         // per-step N per GRU: 3 gates x 512
#define NK_ITERS 8      // 512 / 64
#define KX 128          // precompute K (100 padded)
#define MROWS 131072    // 128 steps x 1024 rows
#define GRPSZ 16        // CTAs per dependency group (one mt, one gru)

// gru smem: 3 stages x (A 16KB + B 12KB) + mbarriers + Gx tile
#define STG_STRIDE 28672
#define SM_FULL  86016
#define SM_EMPTY (86016 + 24)
#define SM_GXBUF 86144
#define GX_ROWB  208            // smem row stride bytes (52 words, conflict-free)
#define SMEM_STEP (SM_GXBUF + 128 * GX_ROWB)   // 112,768 B
// gx_gemm smem (round-14 v1)
#define SMEM_GX (2 * STG_STRIDE)
#define CS_STRIDE 104

// ---- device scratch ----
__device__ __align__(128) __nv_bfloat16 g_Ah[2][2][BQ][KH];
__device__ __align__(128) __nv_bfloat16 g_Wh[2][NS][KH];
__device__ __align__(128) __nv_bfloat16 g_Wx[2][NS][KX];
__device__ __align__(128) __nv_bfloat16 g_AX[2][MROWS][KX];
__device__ __align__(128) __half        g_Gx[2][MROWS][NS];
__device__ __align__(128) float         g_biasH[2][NS];
__device__ __align__(128) float         g_biasX[2][NS];
__device__ __align__(128) float         g_Hf[2][2][BQ][HQ];
__device__ __align__(128) float         g_S[BQ][BQ];
__device__ __align__(128) int g_barGrp[2][8];

// ---- asm helpers ----
#define LDSM4(R0,R1,R2,R3,ADDR) \
  asm volatile("ldmatrix.sync.aligned.m8n8.x4.shared.b16 {%0,%1,%2,%3},[%4];" \
    : "=r"(R0),"=r"(R1),"=r"(R2),"=r"(R3) : "r"(ADDR))

#define MMA16816(C,A0,A1,A2,A3,B0,B1) \
  asm volatile("mma.sync.aligned.m16n8k16.row.col.f32.bf16.bf16.f32 " \
    "{%0,%1,%2,%3},{%4,%5,%6,%7},{%8,%9},{%0,%1,%2,%3};" \
    : "+f"(C[0]),"+f"(C[1]),"+f"(C[2]),"+f"(C[3]) \
    : "r"(A0),"r"(A1),"r"(A2),"r"(A3),"r"(B0),"r"(B1))

#define CPASYNC16(DST,SRC) \
  asm volatile("cp.async.cg.shared.global [%0],[%1],16;" :: "r"(DST),"l"(SRC))
#define CPCOMMIT asm volatile("cp.async.commit_group;" ::: "memory")

#define CPASYNC_ARRIVE(MBAR) \
  asm volatile("cp.async.mbarrier.arrive.noinc.shared::cta.b64 [%0];" :: "r"(MBAR) : "memory")

#define MBARRIER_INIT(addr, cnt) \
  asm volatile("mbarrier.init.shared.b64 [%0], %1;" :: "r"(addr), "r"(cnt) : "memory")
#define MBARRIER_ARRIVE(addr) \
  asm volatile("mbarrier.arrive.shared::cta.b64 _, [%0];" :: "r"(addr) : "memory")

#define MBARRIER_WAIT_PARITY(addr, par) do { \
    uint32_t _m = (addr), _p = (par), _done; \
    asm volatile("{\n\t.reg .pred p;\n\tmbarrier.try_wait.parity.acquire.cta.shared::cta.b64 p, [%1], %2;\n\tselp.b32 %0,1,0,p;\n\t}" \
        : "=r"(_done) : "r"(_m), "r"(_p) : "memory"); \
    if (!_done) { \
        asm volatile("{\n\t.reg .pred P1;\n\tWL_%=:\n\tmbarrier.try_wait.parity.acquire.cta.shared::cta.b64 P1, [%0], %1, 0x989680;\n\t@P1 bra.uni WD_%=;\n\tbra.uni WL_%=;\n\tWD_%=:\n\t}" \
            :: "r"(_m), "r"(_p) : "memory"); \
    } \
} while (0)

// ---------------------------------------------------------------------------
// Column layout (per GRU, N=1536): wgrp=n/48, c=n%48, ni=c>>3, jj=c&7,
// gate=ni>>1 (0=r,1=z,2=nh), h=wgrp*16+(((ni&1)<<3)|jj), grow=gate*512+h.
// ---------------------------------------------------------------------------
__global__ void pack_weights(const float* __restrict__ Wih0, const float* __restrict__ Whh0,
                             const float* __restrict__ bih0, const float* __restrict__ bhh0,
                             const float* __restrict__ Wih1, const float* __restrict__ Whh1,
                             const float* __restrict__ bih1, const float* __restrict__ bhh1) {
    const long totalWh = 2L * NS * KH;
    for (long idx = (long)blockIdx.x * blockDim.x + threadIdx.x; idx < totalWh;
         idx += (long)gridDim.x * blockDim.x) {
        int g   = (int)(idx / (NS * (long)KH));
        int rem = (int)(idx - (long)g * NS * KH);
        int n = rem / KH;
        int k = rem - n * KH;
        int wgrp = n / 48, c = n - wgrp * 48;
        int ni = c >> 3, jj = c & 7;
        int gate = ni >> 1;
        int h = wgrp * 16 + (((ni & 1) << 3) | jj);
        int grow = gate * 512 + h;
        const float* Whh = g ? Whh1 : Whh0;
        g_Wh[g][n][k] = __float2bfloat16(Whh[grow * HQ + k]);
    }
    const long totalWx = 2L * NS * KX;
    for (long idx = (long)blockIdx.x * blockDim.x + threadIdx.x; idx < totalWx;
         idx += (long)gridDim.x * blockDim.x) {
        int g   = (int)(idx / (NS * (long)KX));
        int rem = (int)(idx - (long)g * NS * KX);
        int n = rem / KX;
        int e = rem - n * KX;
        int wgrp = n / 48, c = n - wgrp * 48;
        int ni = c >> 3, jj = c & 7;
        int gate = ni >> 1;
        int h = wgrp * 16 + (((ni & 1) << 3) | jj);
        int grow = gate * 512 + h;
        const float* Wih = g ? Wih1 : Wih0;
        g_Wx[g][n][e] = __float2bfloat16(e < EQ ? Wih[grow * EQ + e] : 0.f);
    }
    for (int idx = blockIdx.x * blockDim.x + threadIdx.x; idx < 2 * NS;
         idx += gridDim.x * blockDim.x) {
        int g = idx / NS;
        int n = idx - g * NS;
        int wgrp = n / 48, c = n - wgrp * 48;
        int ni = c >> 3, jj = c & 7;
        int gate = ni >> 1;
        int h = wgrp * 16 + (((ni & 1) << 3) | jj);
        int grow = gate * 512 + h;
        const float* bih = g ? bih1 : bih0;
        const float* bhh = g ? bhh1 : bhh0;
        g_biasH[g][n] = bhh[grow];
        g_biasX[g][n] = bih[grow] + (gate < 2 ? bhh[grow] : 0.f);
    }
}

// Build A_X rows: row' = s*1024 + R holds x_{t=L-1-s, R} (bf16, pad 0).
__global__ void build_ax(const int* __restrict__ tok0, const int* __restrict__ tok1,
                         const float* __restrict__ emb0, const float* __restrict__ emb1) {
    const long total = 2L * MROWS * KX;
    for (long idx = (long)blockIdx.x * blockDim.x + threadIdx.x; idx < total;
         idx += (long)gridDim.x * blockDim.x) {
        int g    = (int)(idx / (MROWS * (long)KX));
        long rem = idx - (long)g * MROWS * KX;
        int rowp = (int)(rem >> 7);
        int e    = (int)(rem & 127);
        int s = rowp >> 10, R = rowp & 1023;
        float v = 0.f;
        if (e < EQ) {
            const int*   tok = g ? tok1 : tok0;
            const float* emb = g ? emb1 : emb0;
            int ti = tok[R * LQ + (LQ - 1 - s)];
            v = emb[ti * EQ + e];
        }
        g_AX[g][rowp][e] = __float2bfloat16(v);
    }
}

// Zero h state; reset group step barriers
__global__ void init_state() {
    if (blockIdx.x == 0 && threadIdx.x < 16)
        g_barGrp[threadIdx.x >> 3][threadIdx.x & 7] = 0;
    const int totalA = 2 * BQ * KH;
    for (int idx = blockIdx.x * blockDim.x + threadIdx.x; idx < totalA;
         idx += gridDim.x * blockDim.x) {
        int g = idx / (BQ * KH);
        int rem = idx - g * BQ * KH;
        g_Ah[0][g][rem / KH][rem % KH] = __float2bfloat16(0.f);
    }
    const int totalH = 2 * BQ * HQ;
    for (int idx = blockIdx.x * blockDim.x + threadIdx.x; idx < totalH;
         idx += gridDim.x * blockDim.x) {
        int g = idx / (BQ * HQ);
        int rem = idx - g * BQ * HQ;
        g_Hf[0][g][rem / HQ][rem % HQ] = 0.f;
    }
}

// ---------------------------------------------------------------------------
// Precompute Gx = A_X @ Wx^T + biasX (fp16 out). Tile 128x96, K=128.
// Coalesced epilogue via smem staging. grid (n=16, m=1024, 2).
// ---------------------------------------------------------------------------
__global__ __launch_bounds__(256) void gx_gemm() {
    extern __shared__ char smem[];
    const uint32_t sbase = (uint32_t)__cvta_generic_to_shared(smem);
    const int g   = blockIdx.z;
    const int m0p = blockIdx.y * 128;
    const int n0  = blockIdx.x * 96;
    const int tid = threadIdx.x;
    const int lane = tid & 31;
    const int warp = tid >> 5;
    const int wm = (warp >> 1) << 5;
    const int wn = (warp & 1) * 48;

#pragma unroll
    for (int st = 0; st < 2; st++) {
        uint32_t base = sbase + st * STG_STRIDE;
#pragma unroll
        for (int p = 0; p < 4; p++) {
            int unit = tid + 256 * p;
            int r = unit >> 3, c = unit & 7;
            uint32_t dst = base + (uint32_t)(r * 128 + ((c ^ (r & 7)) << 4));
            CPASYNC16(dst, &g_AX[g][m0p + r][st * 64 + c * 8]);
        }
#pragma unroll
        for (int p = 0; p < 3; p++) {
            int unit = tid + 256 * p;
            int r = unit >> 3, c = unit & 7;
            uint32_t dst = base + 16384 + (uint32_t)(r * 128 + ((c ^ (r & 7)) << 4));
            CPASYNC16(dst, &g_Wx[g][n0 + r][st * 64 + c * 8]);
        }
    }
    CPCOMMIT;
    asm volatile("cp.async.wait_group 0;" ::: "memory");
    __syncthreads();

    float acc[2][6][4];
#pragma unroll
    for (int mi = 0; mi < 2; mi++)
#pragma unroll
        for (int ni = 0; ni < 6; ni++)
#pragma unroll
            for (int q = 0; q < 4; q++) acc[mi][ni][q] = 0.f;

#pragma unroll
    for (int it = 0; it < 2; it++) {
        const uint32_t aB = sbase + it * STG_STRIDE;
        const uint32_t bB = aB + 16384;
#pragma unroll
        for (int kc = 0; kc < 4; kc++) {
            uint32_t a[2][4];
#pragma unroll
            for (int mi = 0; mi < 2; mi++) {
                int rrow = wm + mi * 16 + (lane & 15);
                int uc = kc * 2 + (lane >> 4);
                uint32_t addr = aB + (uint32_t)(rrow * 128 + ((uc ^ (rrow & 7)) << 4));
                LDSM4(a[mi][0], a[mi][1], a[mi][2], a[mi][3], addr);
            }
            uint32_t b[3][4];
#pragma unroll
            for (int jj = 0; jj < 3; jj++) {
                int rrow = wn + 16 * jj + (lane & 7) + ((lane >> 4) << 3);
                int uc = kc * 2 + ((lane >> 3) & 1);
                uint32_t addr = bB + (uint32_t)(rrow * 128 + ((uc ^ (rrow & 7)) << 4));
                LDSM4(b[jj][0], b[jj][1], b[jj][2], b[jj][3], addr);
            }
#pragma unroll
            for (int mi = 0; mi < 2; mi++)
#pragma unroll
                for (int ni = 0; ni < 6; ni++) {
                    int j = ni >> 1, hh = (ni & 1) << 1;
                    MMA16816(acc[mi][ni], a[mi][0], a[mi][1], a[mi][2], a[mi][3],
                             b[j][hh], b[j][hh + 1]);
                }
        }
    }
    __syncthreads();

    __half* Cs = (__half*)smem;
#pragma unroll
    for (int mi = 0; mi < 2; mi++)
#pragma unroll
        for (int ni = 0; ni < 6; ni++)
#pragma unroll
            for (int qh = 0; qh < 2; qh++) {
                int lr  = wm + mi * 16 + (lane >> 2) + qh * 8;
                int col = wn + ni * 8 + (lane & 3) * 2;
                float v0 = acc[mi][ni][qh * 2 + 0] + g_biasX[g][n0 + col];
                float v1 = acc[mi][ni][qh * 2 + 1] + g_biasX[g][n0 + col + 1];
                *(__half2*)&Cs[lr * CS_STRIDE + col] = __floats2half2_rn(v0, v1);
            }
    __syncthreads();

#pragma unroll
    for (int p = 0; p < 6; p++) {
        int unit = tid + 256 * p;
        int r = unit / 12, c = unit - r * 12;
        uint4 v = *(const uint4*)&Cs[r * CS_STRIDE + c * 8];
        *(uint4*)&g_Gx[g][m0p + r][n0 + c * 8] = v;
    }
}

// ---------------------------------------------------------------------------
// PERSISTENT GRU: all 128 steps; per-group barrier; mbarrier pipeline state
// carried ACROSS steps (init once). n-gate bias hoisted to registers.
// 256 CTAs (8m x 16n x 2g), 2/SM. Tile 128x96, K=512.
// ---------------------------------------------------------------------------
__global__ __launch_bounds__(256, 2) void gru_persistent() {
    extern __shared__ char smem[];
    const uint32_t sbase = (uint32_t)__cvta_generic_to_shared(smem);
    const int g     = blockIdx.z;
    const int mt    = blockIdx.x;
    const int m0    = mt * 128;
    const int n0    = blockIdx.y * 96;
    const int tid   = threadIdx.x;
    const int lane  = tid & 31;
    const int warp  = tid >> 5;
    const int wm    = (warp >> 1) << 5;
    const int wn    = (warp & 1) * 48;
    const int wgrp  = blockIdx.y * 2 + (warp & 1);
    const uint32_t gxbuf = sbase + SM_GXBUF;
    int* barp = &g_barGrp[g][mt];

    uint32_t aDst[4], aOff[4];
#pragma unroll
    for (int p = 0; p < 4; p++) {
        int unit = tid + 256 * p;
        int r = unit >> 3, c = unit & 7;
        aDst[p] = (uint32_t)(r * 128 + ((c ^ (r & 7)) << 4));
        aOff[p] = (uint32_t)((r * KH + c * 8) * 2);
    }
    uint32_t bDst[3], bOff[3];
#pragma unroll
    for (int p = 0; p < 3; p++) {
        int unit = tid + 256 * p;
        int r = unit >> 3, c = unit & 7;
        bDst[p] = (uint32_t)(r * 128 + ((c ^ (r & 7)) << 4));
        bOff[p] = (uint32_t)((r * KH + c * 8) * 2);
    }
    const __nv_bfloat16* gW = &g_Wh[g][n0][0];

    // hoisted n-gate bias: cR = n0 + wn + sH*8 + jb (independent of mi/qh/s)
    const int jb_h = (lane & 3) * 2;
    float bnA[2][2];
#pragma unroll
    for (int sH = 0; sH < 2; sH++) {
        int cR = n0 + wn + sH * 8 + jb_h;
        bnA[sH][0] = g_biasH[g][cR + 32];
        bnA[sH][1] = g_biasH[g][cR + 33];
    }

    // init mbarriers ONCE
    if (tid == 0) {
#pragma unroll
        for (int st = 0; st < 3; st++) {
            MBARRIER_INIT(sbase + SM_FULL  + 8 * st, 256);
            MBARRIER_INIT(sbase + SM_EMPTY + 8 * st, 8);
        }
    }
    __syncthreads();

#define STAGE_CP(BUF, KOFF, GAPTR) do { \
    uint32_t _aB = sbase + (uint32_t)(BUF) * STG_STRIDE; \
    uint32_t _bB = _aB + 16384; \
    uint32_t _ko = (uint32_t)(KOFF) * 2; \
    CPASYNC16(_aB + aDst[0], (const char*)(GAPTR) + aOff[0] + _ko); \
    CPASYNC16(_aB + aDst[1], (const char*)(GAPTR) + aOff[1] + _ko); \
    CPASYNC16(_aB + aDst[2], (const char*)(GAPTR) + aOff[2] + _ko); \
    CPASYNC16(_aB + aDst[3], (const char*)(GAPTR) + aOff[3] + _ko); \
    CPASYNC16(_bB + bDst[0], (const char*)gW + bOff[0] + _ko); \
    CPASYNC16(_bB + bDst[1], (const char*)gW + bOff[1] + _ko); \
    CPASYNC16(_bB + bDst[2], (const char*)gW + bOff[2] + _ko); \
    CPASYNC_ARRIVE(sbase + SM_FULL + 8 * (BUF)); \
} while (0)

    // pipeline state persistent across steps
    int fill_n = 0;
    int cbuf = 0, cpar = 0;
    int rbuf = 0;
    int ebuf = 0, epar = 0;

#define FILL_STAGE(KOFF, GAPTR) do { \
    if (fill_n >= 3) { \
        MBARRIER_WAIT_PARITY(sbase + SM_EMPTY + 8 * ebuf, epar); \
        if (++ebuf == 3) { ebuf = 0; epar ^= 1; } \
    } \
    STAGE_CP(rbuf, (KOFF), GAPTR); \
    if (++rbuf == 3) rbuf = 0; \
    fill_n++; \
} while (0)

    for (int s = 0; s < LQ; s++) {
        const int cur = s & 1;
        const int nxt = cur ^ 1;
        const __nv_bfloat16* gA = &g_Ah[cur][g][m0][0];

        FILL_STAGE(0, gA);
        FILL_STAGE(64, gA);

        // ---- Gx epilogue-tile prefetch (overlaps the whole main loop) ----
        {
            const char* gxsrc = (const char*)&g_Gx[g][(s << 10) + m0][n0];
#pragma unroll
            for (int p = 0; p < 6; p++) {
                int unit = tid + 256 * p;
                int r = unit / 12, c = unit - r * 12;
                CPASYNC16(gxbuf + (uint32_t)(r * GX_ROWB + c * 16),
                          gxsrc + (size_t)r * (NS * 2) + c * 16);
            }
            CPCOMMIT;
        }

        float acc[2][6][4];
#pragma unroll
        for (int mi = 0; mi < 2; mi++)
#pragma unroll
            for (int ni = 0; ni < 6; ni++)
#pragma unroll
                for (int q = 0; q < 4; q++) acc[mi][ni][q] = 0.f;

        for (int i = 0; i < NK_ITERS; i++) {
            MBARRIER_WAIT_PARITY(sbase + SM_FULL + 8 * cbuf, cpar);

            const uint32_t aB = sbase + (uint32_t)cbuf * STG_STRIDE;
            const uint32_t bB = aB + 16384;

#pragma unroll
            for (int kc = 0; kc < 4; kc++) {
                uint32_t a[2][4];
#pragma unroll
                for (int mi = 0; mi < 2; mi++) {
                    int rrow = wm + mi * 16 + (lane & 15);
                    int uc = kc * 2 + (lane >> 4);
                    uint32_t addr = aB + (uint32_t)(rrow * 128 + ((uc ^ (rrow & 7)) << 4));
                    LDSM4(a[mi][0], a[mi][1], a[mi][2], a[mi][3], addr);
                }
                uint32_t b[3][4];
#pragma unroll
                for (int jj = 0; jj < 3; jj++) {
                    int rrow = wn + 16 * jj + (lane & 7) + ((lane >> 4) << 3);
                    int uc = kc * 2 + ((lane >> 3) & 1);
                    uint32_t addr = bB + (uint32_t)(rrow * 128 + ((uc ^ (rrow & 7)) << 4));
                    LDSM4(b[jj][0], b[jj][1], b[jj][2], b[jj][3], addr);
                }
#pragma unroll
                for (int mi = 0; mi < 2; mi++)
#pragma unroll
                    for (int ni = 0; ni < 6; ni++) {
                        int j = ni >> 1, hh = (ni & 1) << 1;
                        MMA16816(acc[mi][ni], a[mi][0], a[mi][1], a[mi][2], a[mi][3],
                                 b[j][hh], b[j][hh + 1]);
                    }
            }
            __syncwarp();
            if (lane == 0) MBARRIER_ARRIVE(sbase + SM_EMPTY + 8 * cbuf);
            if (++cbuf == 3) { cbuf = 0; cpar ^= 1; }

            if (i + 2 < NK_ITERS) FILL_STAGE((i + 2) * 64, gA);
        }

        asm volatile("cp.async.wait_group 0;" ::: "memory");
        __syncthreads();

        // ---- epilogue: gates from Gh (regs) + Gx (smem) ----
#pragma unroll
        for (int mi = 0; mi < 2; mi++)
#pragma unroll
            for (int sH = 0; sH < 2; sH++)
#pragma unroll
                for (int qh = 0; qh < 2; qh++) {
                    const int rl = wm + mi * 16 + (lane >> 2) + qh * 8;
                    const int R  = m0 + rl;
                    const int jb = (lane & 3) * 2;
                    const int cl = wn + sH * 8 + jb;
                    const char* gxp = smem + SM_GXBUF + rl * GX_ROWB + cl * 2;
                    float2 xr = __half22float2(*(const __half2*)(gxp));
                    float2 xz = __half22float2(*(const __half2*)(gxp + 32));
                    float2 xn = __half22float2(*(const __half2*)(gxp + 64));
                    const int hb = wgrp * 16 + sH * 8 + jb;
                    float2 hov = __ldcg((const float2*)&g_Hf[cur][g][R][hb]);
                    float hn2[2];
#pragma unroll
                    for (int qp = 0; qp < 2; qp++) {
                        const int q = qh * 2 + qp;
                        float GhR = acc[mi][0 + sH][q];
                        float GhZ = acc[mi][2 + sH][q];
                        float GhN = acc[mi][4 + sH][q];
                        float gxrv = qp ? xr.y : xr.x;
                        float gxzv = qp ? xz.y : xz.x;
                        float gxnv = qp ? xn.y : xn.x;
                        float bnv  = bnA[sH][qp];
                        float ho   = qp ? hov.y : hov.x;
                        float rr = 1.f / (1.f + __expf(-(GhR + gxrv)));
                        float zz = 1.f / (1.f + __expf(-(GhZ + gxzv)));
                        float pre = gxnv + rr * (GhN + bnv);
                        float ex = __expf(-2.f * fabsf(pre));
                        float nn = copysignf((1.f - ex) / (1.f + ex), pre);
                        hn2[qp] = (1.f - zz) * nn + zz * ho;
                    }
                    *(float2*)&g_Hf[nxt][g][R][hb] = make_float2(hn2[0], hn2[1]);
                    __nv_bfloat162 hi2;
                    hi2.x = __float2bfloat16(hn2[0]);
                    hi2.y = __float2bfloat16(hn2[1]);
                    *(__nv_bfloat162*)&g_Ah[nxt][g][R][hb] = hi2;
                }

        // ---- per-group step barrier (16 CTAs sharing (mt, gru)) ----
        if (s < LQ - 1) {
            __threadfence();
            __syncthreads();
            if (tid == 0) {
                atomicAdd(barp, 1);
                while (atomicAdd(barp, 0) < GRPSZ * (s + 1)) __nanosleep(64);
            }
            __syncthreads();
        }
    }
}

// ---------------------------------------------------------------------------
// S = hc @ hr^T (fp32, K=512) + row softmax
// ---------------------------------------------------------------------------
__global__ __launch_bounds__(256) void score_gemm() {
    const int bm = blockIdx.y;
    const int bn = blockIdx.x;
    __shared__ float As[16][68];
    __shared__ float Bs[16][68];
    const int tid = threadIdx.x;
    const int tx = tid & 15;
    const int ty = tid >> 4;

    float acc[4][4];
#pragma unroll
    for (int i = 0; i < 4; i++)
#pragma unroll
        for (int j = 0; j < 4; j++) acc[i][j] = 0.f;

    const float* Abase = &g_Hf[0][0][bm * 64][0];
    const float* Bbase = &g_Hf[0][1][bn * 64][0];

    for (int k0 = 0; k0 < HQ; k0 += 16) {
#pragma unroll
        for (int i = 0; i < 4; i++) {
            int e = tid + 256 * i;
            int m = e >> 4;
            int k = e & 15;
            As[k][m] = Abase[m * HQ + k0 + k];
            Bs[k][m] = Bbase[m * HQ + k0 + k];
        }
        __syncthreads();
#pragma unroll
        for (int kk = 0; kk < 16; kk++) {
            float4 a4 = *(const float4*)&As[kk][ty * 4];
            float4 b4 = *(const float4*)&Bs[kk][tx * 4];
            float av[4] = {a4.x, a4.y, a4.z, a4.w};
            float bv[4] = {b4.x, b4.y, b4.z, b4.w};
#pragma unroll
            for (int i = 0; i < 4; i++)
#pragma unroll
                for (int j = 0; j < 4; j++) acc[i][j] += av[i] * bv[j];
        }
        __syncthreads();
    }
    const int row = bm * 64 + ty * 4;
    const int col = bn * 64 + tx * 4;
#pragma unroll
    for (int i = 0; i < 4; i++)
#pragma unroll
        for (int j = 0; j < 4; j++) g_S[row + i][col + j] = acc[i][j];
}

__global__ void softmax_rows(float* __restrict__ out) {
    const int row = blockIdx.x;
    __shared__ float red[256];
    const float* Srow = g_S[row];

    float m = -INFINITY;
    for (int j = threadIdx.x; j < BQ; j += 256) m = fmaxf(m, Srow[j]);
    red[threadIdx.x] = m;
    __syncthreads();
    for (int off = 128; off; off >>= 1) {
        if (threadIdx.x < off) red[threadIdx.x] = fmaxf(red[threadIdx.x], red[threadIdx.x + off]);
        __syncthreads();
    }
    m = red[0];
    __syncthreads();

    float sum = 0.f;
    for (int j = threadIdx.x; j < BQ; j += 256) sum += expf(Srow[j] - m);
    red[threadIdx.x] = sum;
    __syncthreads();
    for (int off = 128; off; off >>= 1) {
        if (threadIdx.x < off) red[threadIdx.x] += red[threadIdx.x + off];
        __syncthreads();
    }
    sum = red[0];

    float inv = 1.f / sum;
    for (int j = threadIdx.x; j < BQ; j += 256) out[row * BQ + j] = expf(Srow[j] - m) * inv;
}

// ---------------------------------------------------------------------------
extern "C" void kernel_launch(void* const* d_in, const int* in_sizes, int n_in,
                              void* d_out, int out_size) {
    const int*   ctx     = (const int*)  d_in[0];
    const int*   rep     = (const int*)  d_in[1];
    const float* ctx_emb = (const float*)d_in[2];
    const float* ctx_Wih = (const float*)d_in[3];
    const float* ctx_Whh = (const float*)d_in[4];
    const float* ctx_bih = (const float*)d_in[5];
    const float* ctx_bhh = (const float*)d_in[6];
    const float* rep_emb = (const float*)d_in[7];
    const float* rep_Wih = (const float*)d_in[8];
    const float* rep_Whh = (const float*)d_in[9];
    const float* rep_bih = (const float*)d_in[10];
    const float* rep_bhh = (const float*)d_in[11];

    cudaFuncSetAttribute(gru_persistent, cudaFuncAttributeMaxDynamicSharedMemorySize, SMEM_STEP);
    cudaFuncSetAttribute(gx_gemm,        cudaFuncAttributeMaxDynamicSharedMemorySize, SMEM_GX);

    pack_weights<<<2048, 256>>>(ctx_Wih, ctx_Whh, ctx_bih, ctx_bhh,
                                rep_Wih, rep_Whh, rep_bih, rep_bhh);
    build_ax<<<8192, 256>>>(ctx, rep, ctx_emb, rep_emb);
    init_state<<<2048, 256>>>();

    gx_gemm<<<dim3(16, 1024, 2), 256, SMEM_GX>>>();

    gru_persistent<<<dim3(8, 16, 2), 256, SMEM_STEP>>>();

    score_gemm<<<dim3(16, 16), 256>>>();
    softmax_rows<<<BQ, 256>>>((float*)d_out);
}